// round 6
// baseline (speedup 1.0000x reference)
#include <cuda_runtime.h>

typedef unsigned long long u64;

#define NT 896
#define BT 56
#define HD 58            /* u64 row stride for dup buffers */
#define B_TOT 8192
#define T_STEPS 30
#define WARM 24

__device__ __forceinline__ u64 pack2(float lo, float hi){
    u64 r; asm("mov.b64 %0, {%1, %2};" : "=l"(r) : "f"(lo), "f"(hi)); return r;
}
__device__ __forceinline__ void unpack2(u64 v, float& lo, float& hi){
    asm("mov.b64 {%0, %1}, %2;" : "=f"(lo), "=f"(hi) : "l"(v));
}
__device__ __forceinline__ u64 fma2(u64 a, u64 b, u64 c){
    u64 d; asm("fma.rn.f32x2 %0, %1, %2, %3;" : "=l"(d) : "l"(a), "l"(b), "l"(c)); return d;
}
__device__ __forceinline__ float sig_(float x){ return __fdividef(1.f, 1.f + __expf(-x)); }
__device__ __forceinline__ float tanh_(float x){ return 1.f - 2.f * __fdividef(1.f, __expf(2.f * x) + 1.f); }

#define CPA16(dst_u32, src) asm volatile("cp.async.cg.shared.global [%0], [%1], 16;" :: "r"(dst_u32), "l"(src))
#define CPA_COMMIT() asm volatile("cp.async.commit_group;")
#define CPA_WAIT()   asm volatile("cp.async.wait_group 0;")

// stage 4096 floats (16KB) global->smem with cp.async, no registers held
__device__ __forceinline__ void stage(float* dst, const float* __restrict__ src, int tid){
    unsigned d = (unsigned)__cvta_generic_to_shared(dst);
    CPA16(d + tid * 16, src + tid * 4);
    if (tid < 128) CPA16(d + (896 + tid) * 16, src + (896 + tid) * 4);
    CPA_COMMIT();
}

// smem: hdup u64[136][HD] + m1dup u64[128][HD] + floats: wsm 8192, cbz 512, cb1/cb2/cwo 384, red 112, predb 56
#define SMEM_BYTES ((136 + 128) * HD * 8 + (8192 + 512 + 384 + 2*BT + BT) * 4)

__global__ void __launch_bounds__(NT, 1)
fused_lstm_kernel(const float* __restrict__ x0, const float* __restrict__ x1,
                  const float* __restrict__ x2, const float* __restrict__ x3,
                  const float* __restrict__ x4, const float* __restrict__ x5,
                  const float* __restrict__ x6, const float* __restrict__ irr,
                  const float* __restrict__ Wi, const float* __restrict__ Wh,
                  const float* __restrict__ bz, const float* __restrict__ W1,
                  const float* __restrict__ b1, const float* __restrict__ W2,
                  const float* __restrict__ b2, const float* __restrict__ Wout,
                  const float* __restrict__ bout, float* __restrict__ out)
{
    extern __shared__ u64 sm[];
    u64*   hdupU  = sm;                        // [136][HD]: k 0-127 h dup, 128-135 inputs dup
    u64*   m1dupU = sm + 136 * HD;             // [128][HD]
    float* wsm    = (float*)(sm + 264 * HD);   // 2 x 4096 weight staging
    float* cbz    = wsm + 8192;                // 512
    float* cb1    = cbz + 512;                 // 128
    float* cb2    = cb1 + 128;                 // 128
    float* cwo    = cb2 + 128;                 // 128
    float* red    = cwo + 128;                 // [2][56]
    float* predb  = red + 2 * BT;              // [56]

    const int tid = threadIdx.x;
    const int cg  = tid & 63;                  // 64 col groups, 2 channels each
    const int rg  = tid >> 6;                  // 0..13, 4 batch rows each
    const int r0  = rg << 2;
    const int ch0 = cg << 1;
    const int b0  = blockIdx.x * BT;

    // init h=0 and small constants
    for (int i = tid; i < 128 * HD; i += NT) hdupU[i] = 0ull;
    for (int i = tid; i < 512; i += NT) cbz[i] = bz[i];
    if (tid < 128){ cb1[tid] = b1[tid]; cb2[tid] = b2[tid]; cwo[tid] = Wout[tid]; }
    const float boutv = bout[0];

    // input feature pointers: 8 feats x 56 rows handled by tid < 448
    const int lf = tid / BT, lr = tid - lf * BT;
    const float* fptr = x0; int tmax = 0;
    if (tid < 8 * BT){
        int lb = b0 + lr; if (lb > B_TOT - 1) lb = B_TOT - 1;
        const float* p;
        if      (lf == 0) p = x0; else if (lf == 1) p = x1;
        else if (lf == 2) p = x2; else if (lf == 3) p = x3;
        else if (lf == 4) p = x4; else if (lf == 5) p = x5;
        else if (lf == 6) p = x6; else              p = irr;
        fptr = (lf < 7) ? (p + lb * T_STEPS) : (p + lb * WARM);
        tmax = (lf < 7) ? (T_STEPS - 1) : (WARM - 1);
    }

    // prologue: stage Wh chunk 0
    stage(wsm, Wh, tid);
    CPA_WAIT();
    int pb = 0;

    u64 cst[4] = {0ull, 0ull, 0ull, 0ull};
    __syncthreads();

    for (int t = 0; t < T_STEPS; ++t){
        // ---- stage this step's inputs (dup) into rows 128..135 ----
        if (tid < 8 * BT){
            int ti = t < tmax ? t : tmax;
            float gv = __ldg(fptr + ti);
            float v = (lf < 7 || t < WARM) ? gv : predb[lr];
            hdupU[(128 + lf) * HD + lr] = pack2(v, v);
        }

        // ================= z = [h, inp] @ [Wh; Wi] + b =================
        // acc[j][q] = (z_{q*128+ch0}, z_{q*128+ch0+1}) for batch row r0+j
        u64 acc[4][4];
        #pragma unroll
        for (int q = 0; q < 4; q++){
            u64 b = *reinterpret_cast<const u64*>(cbz + (q << 7) + ch0);
            acc[0][q] = b; acc[1][q] = b; acc[2][q] = b; acc[3][q] = b;
        }

        for (int c = 0; c <= 16; ++c){
            const float* nsrc = (c < 15) ? (Wh + (c + 1) * 4096) : ((c == 15) ? Wi : W1);
            stage(wsm + ((pb ^ 1) << 12), nsrc, tid);

            const float* wb = wsm + (pb << 12);
            const int k0 = c << 3;
            #pragma unroll
            for (int kk = 0; kk < 8; kk++){
                const u64* hd = hdupU + (k0 + kk) * HD + r0;
                ulonglong2 A  = *reinterpret_cast<const ulonglong2*>(hd);
                ulonglong2 Bv = *reinterpret_cast<const ulonglong2*>(hd + 2);
                #pragma unroll
                for (int q = 0; q < 4; q++){
                    u64 wp = *reinterpret_cast<const u64*>(wb + (kk << 9) + (q << 7) + ch0);
                    acc[0][q] = fma2(A.x,  wp, acc[0][q]);
                    acc[1][q] = fma2(A.y,  wp, acc[1][q]);
                    acc[2][q] = fma2(Bv.x, wp, acc[2][q]);
                    acc[3][q] = fma2(Bv.y, wp, acc[3][q]);
                }
            }
            CPA_WAIT();
            __syncthreads();
            pb ^= 1;
        }

        // ================= gates; c-state in regs; write h dup =================
        #pragma unroll
        for (int j = 0; j < 4; j++){
            float i0,i1,f0,f1,g0,g1,o0,o1,c0,c1;
            unpack2(acc[j][0], i0, i1);
            unpack2(acc[j][1], f0, f1);
            unpack2(acc[j][2], g0, g1);
            unpack2(acc[j][3], o0, o1);
            unpack2(cst[j], c0, c1);
            c0 = sig_(f0)*c0 + sig_(i0)*tanh_(g0);
            c1 = sig_(f1)*c1 + sig_(i1)*tanh_(g1);
            cst[j] = pack2(c0, c1);
            float h0 = sig_(o0)*tanh_(c0);
            float h1 = sig_(o1)*tanh_(c1);
            int row = r0 + j;
            hdupU[ ch0      * HD + row] = pack2(h0, h0);
            hdupU[(ch0 + 1) * HD + row] = pack2(h1, h1);
        }
        __syncthreads();

        // ================= m1 = relu(h @ W1 + b1) =================
        u64 a1[4];
        {
            u64 b = *reinterpret_cast<const u64*>(cb1 + ch0);
            a1[0] = b; a1[1] = b; a1[2] = b; a1[3] = b;
        }
        for (int c = 0; c < 4; ++c){
            const float* nsrc = (c < 3) ? (W1 + (c + 1) * 4096) : W2;
            stage(wsm + ((pb ^ 1) << 12), nsrc, tid);

            const float* wb = wsm + (pb << 12);
            const int k0 = c << 5;
            #pragma unroll 8
            for (int kk = 0; kk < 32; kk++){
                const u64* hd = hdupU + (k0 + kk) * HD + r0;
                ulonglong2 A  = *reinterpret_cast<const ulonglong2*>(hd);
                ulonglong2 Bv = *reinterpret_cast<const ulonglong2*>(hd + 2);
                u64 wp = *reinterpret_cast<const u64*>(wb + (kk << 7) + ch0);
                a1[0] = fma2(A.x,  wp, a1[0]);
                a1[1] = fma2(A.y,  wp, a1[1]);
                a1[2] = fma2(Bv.x, wp, a1[2]);
                a1[3] = fma2(Bv.y, wp, a1[3]);
            }
            CPA_WAIT();
            __syncthreads();
            pb ^= 1;
        }
        #pragma unroll
        for (int j = 0; j < 4; j++){
            float v0, v1; unpack2(a1[j], v0, v1);
            v0 = fmaxf(v0, 0.f); v1 = fmaxf(v1, 0.f);
            int row = r0 + j;
            m1dupU[ ch0      * HD + row] = pack2(v0, v0);
            m1dupU[(ch0 + 1) * HD + row] = pack2(v1, v1);
        }
        __syncthreads();

        // ================= m2 = relu(m1 @ W2 + b2) =================
        u64 a2[4];
        {
            u64 b = *reinterpret_cast<const u64*>(cb2 + ch0);
            a2[0] = b; a2[1] = b; a2[2] = b; a2[3] = b;
        }
        for (int c = 0; c < 4; ++c){
            const float* nsrc = (c < 3) ? (W2 + (c + 1) * 4096) : Wh;  // last: next step chunk 0
            stage(wsm + ((pb ^ 1) << 12), nsrc, tid);

            const float* wb = wsm + (pb << 12);
            const int k0 = c << 5;
            #pragma unroll 8
            for (int kk = 0; kk < 32; kk++){
                const u64* hd = m1dupU + (k0 + kk) * HD + r0;
                ulonglong2 A  = *reinterpret_cast<const ulonglong2*>(hd);
                ulonglong2 Bv = *reinterpret_cast<const ulonglong2*>(hd + 2);
                u64 wp = *reinterpret_cast<const u64*>(wb + (kk << 7) + ch0);
                a2[0] = fma2(A.x,  wp, a2[0]);
                a2[1] = fma2(A.y,  wp, a2[1]);
                a2[2] = fma2(Bv.x, wp, a2[2]);
                a2[3] = fma2(Bv.y, wp, a2[3]);
            }
            CPA_WAIT();
            __syncthreads();
            pb ^= 1;
        }

        // ---- out-projection + warp shuffle reduce over 32 channel-groups ----
        {
            float wo0 = cwo[ch0], wo1 = cwo[ch0 + 1];
            float p[4];
            #pragma unroll
            for (int j = 0; j < 4; j++){
                float v0, v1; unpack2(a2[j], v0, v1);
                p[j] = fmaxf(v0, 0.f) * wo0 + fmaxf(v1, 0.f) * wo1;
            }
            #pragma unroll
            for (int off = 16; off; off >>= 1){
                p[0] += __shfl_xor_sync(0xffffffffu, p[0], off);
                p[1] += __shfl_xor_sync(0xffffffffu, p[1], off);
                p[2] += __shfl_xor_sync(0xffffffffu, p[2], off);
                p[3] += __shfl_xor_sync(0xffffffffu, p[3], off);
            }
            if ((tid & 31) == 0){
                int half = (tid >> 5) & 1;
                red[half * BT + r0 + 0] = p[0];
                red[half * BT + r0 + 1] = p[1];
                red[half * BT + r0 + 2] = p[2];
                red[half * BT + r0 + 3] = p[3];
            }
        }
        __syncthreads();
        if (tid < BT){
            float s = boutv + red[tid] + red[BT + tid];
            predb[tid] = s;
            int bb = b0 + tid;
            if (bb < B_TOT) out[bb * T_STEPS + t] = s;
        }
        __syncthreads();
    }
}

extern "C" void kernel_launch(void* const* d_in, const int* in_sizes, int n_in,
                              void* d_out, int out_size)
{
    (void)in_sizes; (void)n_in; (void)out_size;
    cudaFuncSetAttribute(fused_lstm_kernel, cudaFuncAttributeMaxDynamicSharedMemorySize, SMEM_BYTES);
    int grid = (B_TOT + BT - 1) / BT; // 147
    fused_lstm_kernel<<<grid, NT, SMEM_BYTES>>>(
        (const float*)d_in[8],  (const float*)d_in[9],  (const float*)d_in[10],
        (const float*)d_in[11], (const float*)d_in[12], (const float*)d_in[13],
        (const float*)d_in[14], (const float*)d_in[15],
        (const float*)d_in[16], (const float*)d_in[17], (const float*)d_in[18],
        (const float*)d_in[19], (const float*)d_in[20], (const float*)d_in[21],
        (const float*)d_in[22], (const float*)d_in[23], (const float*)d_in[24],
        (float*)d_out);
}